// round 1
// baseline (speedup 1.0000x reference)
#include <cuda_runtime.h>
#include <cstddef>

// Problem constants (from reference):
//   C_IN=8, H=W=32, C_OUT=32, K=4, S=2, P=1, HO=WO=16
//   IN_FEAT = 8*32*32 = 8192, OUT_FEAT = 32*16*16 = 8192
// Output layout (flattened tuple, C order):
//   [0      , 16384)                : out_bounds [2, 32, 16, 16]
//   [16384  , 16384 + 8192*8192)    : W_mat [8192, 8192]
//   [16384 + 8192*8192, +8192)      : bias_backsub [8192]

#define C_IN     8
#define C_OUT    32
#define HO       16
#define WO       16
#define IN_FEAT  8192
#define OUT_FEAT 8192
#define WMAT_OFF 16384ULL
#define BB_OFF   (16384ULL + 8192ULL * 8192ULL)

// ---------------------------------------------------------------------------
// Kernel 1: scatter conv weights into the (pre-zeroed) Toeplitz matrix.
// One thread per (output position o, tap t) pair: 8192 * 128 = 1,048,576.
//   o = co*256 + ho*16 + wo ; t = ci*16 + kh*4 + kw
//   W_mat[o, ci*1024 + h*32 + w] = weight[co, ci, kh, kw]
//   where h = 2*ho - 1 + kh, w = 2*wo - 1 + kw (skip out-of-range = padding)
// ---------------------------------------------------------------------------
__global__ void scatter_wmat_kernel(const float* __restrict__ weight,
                                    float* __restrict__ wmat) {
    unsigned gid = blockIdx.x * blockDim.x + threadIdx.x;   // < 8192*128
    unsigned o = gid >> 7;       // output index
    unsigned t = gid & 127u;     // tap index within (ci, kh, kw)

    unsigned co = o >> 8;
    unsigned ho = (o >> 4) & 15u;
    unsigned wo = o & 15u;

    unsigned ci = t >> 4;
    unsigned kh = (t >> 2) & 3u;
    unsigned kw = t & 3u;

    int h = 2 * (int)ho - 1 + (int)kh;
    int w = 2 * (int)wo - 1 + (int)kw;

    if ((unsigned)h < 32u && (unsigned)w < 32u) {
        unsigned in = ci * 1024u + (unsigned)h * 32u + (unsigned)w;
        wmat[(size_t)o * IN_FEAT + in] = weight[co * 128u + t];
    }
}

// ---------------------------------------------------------------------------
// Kernel 2: interval conv (lower/upper bounds) + bias_backsub.
// One thread per output position (8192 threads).
//   lower[o] = b[co] + sum( max(w,0)*l + min(w,0)*u )
//   upper[o] = b[co] + sum( max(w,0)*u + min(w,0)*l )
// This equals both the forward-propagated AND back-substituted bounds, so the
// reference's "tighten" is a no-op up to fp rounding.
// Weight index is uniform across the warp (same co per 256-thread block) ->
// broadcast loads.
// ---------------------------------------------------------------------------
__global__ void bounds_kernel(const float* __restrict__ bounds,   // [2, 8192]
                              const float* __restrict__ weight,   // [32,8,4,4]
                              const float* __restrict__ bias,     // [32]
                              float* __restrict__ out) {
    unsigned o = blockIdx.x * blockDim.x + threadIdx.x;  // < 8192
    unsigned co = o >> 8;
    unsigned ho = (o >> 4) & 15u;
    unsigned wo = o & 15u;

    const float* __restrict__ l = bounds;
    const float* __restrict__ u = bounds + IN_FEAT;

    float b = __ldg(&bias[co]);
    float lo = b;
    float up = b;

    #pragma unroll
    for (int ci = 0; ci < C_IN; ci++) {
        #pragma unroll
        for (int kh = 0; kh < 4; kh++) {
            int h = 2 * (int)ho - 1 + kh;
            if ((unsigned)h >= 32u) continue;
            #pragma unroll
            for (int kw = 0; kw < 4; kw++) {
                int w = 2 * (int)wo - 1 + kw;
                if ((unsigned)w >= 32u) continue;
                float wv = __ldg(&weight[co * 128u + (unsigned)ci * 16u +
                                         (unsigned)kh * 4u + (unsigned)kw]);
                float wp = fmaxf(wv, 0.0f);
                float wm = fminf(wv, 0.0f);
                unsigned in = (unsigned)ci * 1024u + (unsigned)h * 32u + (unsigned)w;
                float lv = __ldg(&l[in]);
                float uv = __ldg(&u[in]);
                lo = fmaf(wp, lv, fmaf(wm, uv, lo));
                up = fmaf(wp, uv, fmaf(wm, lv, up));
            }
        }
    }

    out[o] = lo;                 // out_bounds[0]
    out[OUT_FEAT + o] = up;      // out_bounds[1]
    out[BB_OFF + o] = b;         // bias_backsub = repeat_interleave(bias, 256)
}

// ---------------------------------------------------------------------------
// Launch: memset W_mat region (peak-BW memset node) -> scatter -> bounds.
// All on the default stream (ordered), no sync, no allocation.
// ---------------------------------------------------------------------------
extern "C" void kernel_launch(void* const* d_in, const int* in_sizes, int n_in,
                              void* d_out, int out_size) {
    const float* bounds = (const float*)d_in[0];  // [2, 8, 32, 32]
    const float* weight = (const float*)d_in[1];  // [32, 8, 4, 4]
    const float* bias   = (const float*)d_in[2];  // [32]
    // d_in[3] = assignment (unused by reference forward)

    float* out = (float*)d_out;

    // Zero the Toeplitz matrix region (268 MB) — dominates runtime.
    cudaMemsetAsync(out + WMAT_OFF, 0,
                    (size_t)OUT_FEAT * (size_t)IN_FEAT * sizeof(float), 0);

    // Scatter the <=1M nonzero conv weights.
    scatter_wmat_kernel<<<(OUT_FEAT * 128) / 256, 256>>>(weight, out + WMAT_OFF);

    // Interval-conv bounds + bias_backsub.
    bounds_kernel<<<OUT_FEAT / 256, 256>>>(bounds, weight, bias, out);
}

// round 2
// speedup vs baseline: 1.5382x; 1.5382x over previous
#include <cuda_runtime.h>
#include <cstddef>

// Problem constants:
//   C_IN=8, H=W=32, C_OUT=32, K=4, S=2, P=1, HO=WO=16
//   IN_FEAT = 8192, OUT_FEAT = 8192
// Output layout (flattened tuple):
//   [0, 16384)                    : out_bounds [2, 32, 16, 16]
//   [16384, 16384 + 8192*8192)    : W_mat [8192, 8192]
//   [16384 + 8192*8192, +8192)    : bias_backsub [8192]

#define C_IN     8
#define C_OUT    32
#define IN_FEAT  8192
#define OUT_FEAT 8192
#define WMAT_OFF 16384ULL
#define BB_OFF   (16384ULL + 8192ULL * 8192ULL)

// float4 granularity over W_mat: 8192*8192/4 = 16,777,216 float4s.
#define TOTAL_Q      16777216u
#define Q_PER_ROW    2048u       // 8192 cols / 4
#define BOUNDS_BLOCKS 32
#define FILL_BLOCKS   2368       // 148 SMs * 16
#define BLOCK_THREADS 256

__global__ void __launch_bounds__(BLOCK_THREADS)
fused_deeppoly_kernel(const float* __restrict__ bounds,   // [2, 8192] (l, u)
                      const float* __restrict__ weight,   // [32, 8, 4, 4]
                      const float* __restrict__ bias,     // [32]
                      float* __restrict__ out) {
    unsigned bid = blockIdx.x;
    unsigned tid = threadIdx.x;

    if (bid < BOUNDS_BLOCKS) {
        // ------------------------------------------------------------------
        // Bounds part: interval conv. o = output index (co, ho, wo).
        // lower = b + sum(max(w,0)*l + min(w,0)*u); upper symmetric.
        // Equals both forward-propagated and back-substituted bounds, so the
        // reference's tighten is a no-op up to fp rounding (verified R1).
        // ------------------------------------------------------------------
        unsigned o = bid * BLOCK_THREADS + tid;      // < 8192
        unsigned co = o >> 8;
        unsigned ho = (o >> 4) & 15u;
        unsigned wo = o & 15u;

        const float* __restrict__ l = bounds;
        const float* __restrict__ u = bounds + IN_FEAT;

        float b = __ldg(&bias[co]);
        float lo = b;
        float up = b;

        #pragma unroll
        for (int ci = 0; ci < C_IN; ci++) {
            #pragma unroll
            for (int kh = 0; kh < 4; kh++) {
                int h = 2 * (int)ho - 1 + kh;
                if ((unsigned)h >= 32u) continue;
                #pragma unroll
                for (int kw = 0; kw < 4; kw++) {
                    int w = 2 * (int)wo - 1 + kw;
                    if ((unsigned)w >= 32u) continue;
                    float wv = __ldg(&weight[co * 128u + (unsigned)ci * 16u +
                                             (unsigned)kh * 4u + (unsigned)kw]);
                    float wp = fmaxf(wv, 0.0f);
                    float wm = fminf(wv, 0.0f);
                    unsigned in = (unsigned)ci * 1024u +
                                  (unsigned)h * 32u + (unsigned)w;
                    float lv = __ldg(&l[in]);
                    float uv = __ldg(&u[in]);
                    lo = fmaf(wp, lv, fmaf(wm, uv, lo));
                    up = fmaf(wp, uv, fmaf(wm, lv, up));
                }
            }
        }

        out[o] = lo;                 // out_bounds[0]
        out[OUT_FEAT + o] = up;      // out_bounds[1]
        out[BB_OFF + o] = b;         // bias_backsub
        return;
    }

    // ----------------------------------------------------------------------
    // Fill+scatter part: write W_mat in float4 strips, computing the value
    // (mostly zero, occasionally a conv weight) on the fly. One pass, no
    // separate memset.
    //
    // q indexes float4s. Row o = q >> 11; in-row float4 f = q & 2047.
    // Column c = 4*f decomposes as ci = c>>10, h = (c>>5)&31, w = c&31.
    // Since 32 % 4 == 0, a float4 never crosses an h (or ci) boundary:
    // fixed (ci, h), w in {w0..w0+3}.
    // Nonzero iff kh = h - 2*ho + 1 in [0,4) and kw = w - 2*wo + 1 in [0,4).
    // ----------------------------------------------------------------------
    float4* __restrict__ wmat4 = (float4*)(out + WMAT_OFF);

    unsigned start = (bid - BOUNDS_BLOCKS) * BLOCK_THREADS + tid;
    const unsigned stride = FILL_BLOCKS * BLOCK_THREADS;

    for (unsigned q = start; q < TOTAL_Q; q += stride) {
        unsigned o  = q >> 11;
        unsigned f  = q & 2047u;
        unsigned ci = f >> 8;
        unsigned h  = (f >> 3) & 31u;
        unsigned w0 = (f & 7u) << 2;

        unsigned co = o >> 8;
        unsigned ho = (o >> 4) & 15u;
        unsigned wo = o & 15u;

        float4 v = make_float4(0.f, 0.f, 0.f, 0.f);

        int kh = (int)h - 2 * (int)ho + 1;
        if ((unsigned)kh < 4u) {
            int kw0 = (int)w0 - 2 * (int)wo + 1;   // kw for lane j=0
            // window {2wo-1..2wo+2} overlaps {w0..w0+3} iff kw0 in (-4, 4)
            if (kw0 > -4 && kw0 < 4) {
                const float* __restrict__ wp =
                    weight + co * 128u + ci * 16u + (unsigned)kh * 4u;
                if ((unsigned)(kw0 + 0) < 4u) v.x = __ldg(&wp[kw0 + 0]);
                if ((unsigned)(kw0 + 1) < 4u) v.y = __ldg(&wp[kw0 + 1]);
                if ((unsigned)(kw0 + 2) < 4u) v.z = __ldg(&wp[kw0 + 2]);
                if ((unsigned)(kw0 + 3) < 4u) v.w = __ldg(&wp[kw0 + 3]);
            }
        }

        wmat4[q] = v;
    }
}

extern "C" void kernel_launch(void* const* d_in, const int* in_sizes, int n_in,
                              void* d_out, int out_size) {
    const float* bounds = (const float*)d_in[0];  // [2, 8, 32, 32]
    const float* weight = (const float*)d_in[1];  // [32, 8, 4, 4]
    const float* bias   = (const float*)d_in[2];  // [32]
    // d_in[3] = assignment (unused by reference forward)

    float* out = (float*)d_out;

    fused_deeppoly_kernel<<<BOUNDS_BLOCKS + FILL_BLOCKS, BLOCK_THREADS>>>(
        bounds, weight, bias, out);
}

// round 3
// speedup vs baseline: 1.5753x; 1.0241x over previous
#include <cuda_runtime.h>
#include <cstddef>

// Problem constants:
//   C_IN=8, H=W=32, C_OUT=32, K=4, S=2, P=1, HO=WO=16
//   IN_FEAT = 8192, OUT_FEAT = 8192
// Output layout (flattened tuple):
//   [0, 16384)                    : out_bounds [2, 32, 16, 16]
//   [16384, 16384 + 8192*8192)    : W_mat [8192, 8192]
//   [16384 + 8192*8192, +8192)    : bias_backsub [8192]

#define C_IN     8
#define C_OUT    32
#define IN_FEAT  8192
#define OUT_FEAT 8192
#define WMAT_OFF 16384ULL
#define BB_OFF   (16384ULL + 8192ULL * 8192ULL)

#define BOUNDS_BLOCKS 32
#define FILL_BLOCKS   2368       // 148 SMs * 16
#define BLOCK_THREADS 256
#define WARPS_PER_BLOCK (BLOCK_THREADS / 32)

// W_mat is processed in 4KB "chunks": one chunk = one (row o, input channel ci)
// = 32h x 32w floats = 256 float4. Total chunks = 8192 rows * 8 ci = 65536.
#define TOTAL_CHUNKS 65536u

__global__ void __launch_bounds__(BLOCK_THREADS)
fused_deeppoly_kernel(const float* __restrict__ bounds,   // [2, 8192] (l, u)
                      const float* __restrict__ weight,   // [32, 8, 4, 4]
                      const float* __restrict__ bias,     // [32]
                      float* __restrict__ out) {
    unsigned bid = blockIdx.x;
    unsigned tid = threadIdx.x;

    if (bid < BOUNDS_BLOCKS) {
        // ------------------------------------------------------------------
        // Interval conv bounds. Equals both forward-propagated and
        // back-substituted bounds -> reference's tighten is a no-op
        // (verified R1/R2, rel_err 2e-7).
        // ------------------------------------------------------------------
        unsigned o = bid * BLOCK_THREADS + tid;      // < 8192
        unsigned co = o >> 8;
        unsigned ho = (o >> 4) & 15u;
        unsigned wo = o & 15u;

        const float* __restrict__ l = bounds;
        const float* __restrict__ u = bounds + IN_FEAT;

        float b = __ldg(&bias[co]);
        float lo = b;
        float up = b;

        #pragma unroll
        for (int ci = 0; ci < C_IN; ci++) {
            #pragma unroll
            for (int kh = 0; kh < 4; kh++) {
                int h = 2 * (int)ho - 1 + kh;
                if ((unsigned)h >= 32u) continue;
                #pragma unroll
                for (int kw = 0; kw < 4; kw++) {
                    int w = 2 * (int)wo - 1 + kw;
                    if ((unsigned)w >= 32u) continue;
                    float wv = __ldg(&weight[co * 128u + (unsigned)ci * 16u +
                                             (unsigned)kh * 4u + (unsigned)kw]);
                    float wp = fmaxf(wv, 0.0f);
                    float wm = fminf(wv, 0.0f);
                    unsigned in = (unsigned)ci * 1024u +
                                  (unsigned)h * 32u + (unsigned)w;
                    float lv = __ldg(&l[in]);
                    float uv = __ldg(&u[in]);
                    lo = fmaf(wp, lv, fmaf(wm, uv, lo));
                    up = fmaf(wp, uv, fmaf(wm, lv, up));
                }
            }
        }

        out[o] = lo;                 // out_bounds[0]
        out[OUT_FEAT + o] = up;      // out_bounds[1]
        out[BB_OFF + o] = b;         // bias_backsub
        return;
    }

    // ----------------------------------------------------------------------
    // Fill+scatter: one warp per 4KB chunk (grid-stride). Chunk decomposition
    // happens ONCE per chunk; the chunk body is 8 warp-wide STG.128
    // iterations of 512B each. The "strip intersects conv window" test is
    // warp-uniform, so 6-7 of 8 iterations are pure zero-stores.
    //
    // Within a chunk (fixed o, ci): float index = h*32 + w.
    // Iteration it covers h in [4*it, 4*it+4); lane covers
    // h = 4*it + (lane>>3), w in [4*(lane&7), 4*(lane&7)+4).
    // Nonzero iff kh = h - (2*ho - 1) in [0,4) and kw = w - (2*wo - 1) in [0,4).
    // ----------------------------------------------------------------------
    float4* __restrict__ wmat4 = (float4*)(out + WMAT_OFF);

    unsigned lane = tid & 31u;
    unsigned warp = (bid - BOUNDS_BLOCKS) * WARPS_PER_BLOCK + (tid >> 5);
    const unsigned nwarps = FILL_BLOCKS * WARPS_PER_BLOCK;

    for (unsigned chunk = warp; chunk < TOTAL_CHUNKS; chunk += nwarps) {
        unsigned o  = chunk >> 3;
        unsigned ci = chunk & 7u;
        unsigned co = o >> 8;
        unsigned ho = (o >> 4) & 15u;
        unsigned wo = o & 15u;

        float4* __restrict__ base = wmat4 + (size_t)chunk * 256u;
        const float* __restrict__ wrow = weight + co * 128u + ci * 16u;

        int hwin0 = 2 * (int)ho - 1;                     // window h start
        int kw0 = (int)((lane & 7u) << 2) - 2 * (int)wo + 1;
        int hl = (int)(lane >> 3);                       // 0..3

        #pragma unroll
        for (int it = 0; it < 8; it++) {
            float4 v = make_float4(0.f, 0.f, 0.f, 0.f);
            // Warp-uniform: strip [4it, 4it+4) vs window [hwin0, hwin0+4)
            if (4 * it + 3 >= hwin0 && 4 * it <= hwin0 + 3) {
                int kh = 4 * it + hl - hwin0;
                if ((unsigned)kh < 4u && kw0 > -4 && kw0 < 4) {
                    const float* __restrict__ wp = wrow + (unsigned)kh * 4u;
                    if ((unsigned)(kw0 + 0) < 4u) v.x = __ldg(&wp[kw0 + 0]);
                    if ((unsigned)(kw0 + 1) < 4u) v.y = __ldg(&wp[kw0 + 1]);
                    if ((unsigned)(kw0 + 2) < 4u) v.z = __ldg(&wp[kw0 + 2]);
                    if ((unsigned)(kw0 + 3) < 4u) v.w = __ldg(&wp[kw0 + 3]);
                }
            }
            __stcs(&base[it * 32 + lane], v);   // streaming store, 512B/warp
        }
    }
}

extern "C" void kernel_launch(void* const* d_in, const int* in_sizes, int n_in,
                              void* d_out, int out_size) {
    const float* bounds = (const float*)d_in[0];  // [2, 8, 32, 32]
    const float* weight = (const float*)d_in[1];  // [32, 8, 4, 4]
    const float* bias   = (const float*)d_in[2];  // [32]
    // d_in[3] = assignment (unused by reference forward)

    float* out = (float*)d_out;

    fused_deeppoly_kernel<<<BOUNDS_BLOCKS + FILL_BLOCKS, BLOCK_THREADS>>>(
        bounds, weight, bias, out);
}